// round 16
// baseline (speedup 1.0000x reference)
#include <cuda_runtime.h>
#include <cuda_bf16.h>

typedef unsigned long long ull;

#define N_NODES 50000
#define N_EDGES 800000
#define C 128            // channels (x dim, hidden, out)
#define TM  128          // nodes per block in MLP
#define THREADS 256

// 25.6 MB scratch for the per-node edge sums (cudaMalloc is forbidden).
__device__ float g_edge_sum[(size_t)N_NODES * C];

// ---------------------------------------------------------------------------
// Kernel 0: no-op. Keeps ncu's fixed profiled-launch slot on mlp_kernel.
// ---------------------------------------------------------------------------
__global__ void dummy_kernel() {}

// ---------------------------------------------------------------------------
// Kernel 1: zero the scatter target.
// ---------------------------------------------------------------------------
__global__ void zero_kernel() {
    int i = blockIdx.x * blockDim.x + threadIdx.x;   // float4 index
    if (i < (N_NODES * C) / 4)
        reinterpret_cast<float4*>(g_edge_sum)[i] = make_float4(0.f, 0.f, 0.f, 0.f);
}

// ---------------------------------------------------------------------------
// Kernel 2: scatter-add edge_attr rows into g_edge_sum[edge_index[0,e]].
// edge_index is INT32 (JAX x64 disabled -> int64 request yields int32).
// One warp per edge; each lane handles one float4 (512B/edge, coalesced read).
// ---------------------------------------------------------------------------
__global__ void __launch_bounds__(THREADS) scatter_kernel(
    const float* __restrict__ edge_attr,
    const int* __restrict__ edge_index)   // int32! row 0 = first N_EDGES entries
{
    const int e    = blockIdx.x * 8 + (threadIdx.x >> 5);
    const int lane = threadIdx.x & 31;
    const int n = edge_index[e];
    if ((unsigned)n >= (unsigned)N_NODES) return;   // defensive: never IMA
    const float4 v = reinterpret_cast<const float4*>(edge_attr)[(size_t)e * 32 + lane];
    float* dst = &g_edge_sum[(size_t)n * C + lane * 4];
    asm volatile("red.global.add.v4.f32 [%0], {%1, %2, %3, %4};"
                 :: "l"(dst), "f"(v.x), "f"(v.y), "f"(v.z), "f"(v.w)
                 : "memory");
}

// ---------------------------------------------------------------------------
// Kernel 3: fused 3-layer MLP with ELU, fp32 via packed fma.rn.f32x2.
// R5 structure + two gemm-loop fixes from the R14 profile (L1=74%, issue=38%):
//   - a-loads vectorized to 2x LDS.128 (ulonglong2): 8->6 wavefronts/warp-k
//   - k+1 registers prefetched before k's FMAs (sw pipeline, unroll 8)
// ---------------------------------------------------------------------------
__device__ __forceinline__ float elu1(float v) {
    return v > 0.f ? v : expm1f(v);
}

#define DUP2(d, s)  asm("mov.b64 %0, {%1, %1};" : "=l"(d) : "f"(s))
#define FMA2(acc, a, b) \
    asm("fma.rn.f32x2 %0, %1, %2, %0;" : "+l"(acc) : "l"(a), "l"(b))
#define UNPK2(lo, hi, s) \
    asm("mov.b64 {%0, %1}, %2;" : "=f"(lo), "=f"(hi) : "l"(s))

// Stage a [128 k][128 node] k-major activation tile from a row-major source.
__device__ __forceinline__ void load_act_t(float* s_act, const float* __restrict__ src,
                                           int nbase, int tid) {
    const int nl = tid & 127;
    int node = nbase + nl;
    if (node > N_NODES - 1) node = N_NODES - 1;   // clamp tail (stores guarded later)
    const float* row = src + (size_t)node * C;
    #pragma unroll
    for (int k0 = (tid >> 7) * 4; k0 < 128; k0 += 8) {
        const float4 v = *reinterpret_cast<const float4*>(row + k0);
        s_act[(k0 + 0) * TM + nl] = v.x;
        s_act[(k0 + 1) * TM + nl] = v.y;
        s_act[(k0 + 2) * TM + nl] = v.z;
        s_act[(k0 + 3) * TM + nl] = v.w;
    }
}

// Coalesced copy of a [128][128] fp32 weight tile into smem.
__device__ __forceinline__ void load_w(float* s_w, const float* __restrict__ W, int tid) {
    #pragma unroll
    for (int i = tid; i < (128 * 128) / 4; i += THREADS)
        reinterpret_cast<float4*>(s_w)[i] = reinterpret_cast<const float4*>(W)[i];
}

// 8x8 register-tile GEMM over K=128, vector LDS + one-k-ahead prefetch.
__device__ __forceinline__ void gemm128(const float* s_act, const float* s_w,
                                        ull acc[4][8], int n0, int j0) {
    const float* ar = s_act + n0;   // + k*TM per step
    const float* wr = s_w + j0;     // + k*C  per step
    ulonglong2 A01 = *reinterpret_cast<const ulonglong2*>(ar);
    ulonglong2 A23 = *reinterpret_cast<const ulonglong2*>(ar + 4);
    float4     W0  = *reinterpret_cast<const float4*>(wr);
    float4     W1  = *reinterpret_cast<const float4*>(wr + 4);
    #pragma unroll 8
    for (int k = 0; k < 128; ++k) {
        const ulonglong2 a01 = A01, a23 = A23;
        const float4     w0  = W0,  w1  = W1;
        if (k + 1 < 128) {          // prefetch next k before this k's math
            const float* arn = ar + (k + 1) * TM;
            const float* wrn = wr + (k + 1) * C;
            A01 = *reinterpret_cast<const ulonglong2*>(arn);
            A23 = *reinterpret_cast<const ulonglong2*>(arn + 4);
            W0  = *reinterpret_cast<const float4*>(wrn);
            W1  = *reinterpret_cast<const float4*>(wrn + 4);
        }
        ull wd[8];
        DUP2(wd[0], w0.x); DUP2(wd[1], w0.y); DUP2(wd[2], w0.z); DUP2(wd[3], w0.w);
        DUP2(wd[4], w1.x); DUP2(wd[5], w1.y); DUP2(wd[6], w1.z); DUP2(wd[7], w1.w);
        #pragma unroll
        for (int j = 0; j < 8; ++j) {
            FMA2(acc[0][j], a01.x, wd[j]);
            FMA2(acc[1][j], a01.y, wd[j]);
            FMA2(acc[2][j], a23.x, wd[j]);
            FMA2(acc[3][j], a23.y, wd[j]);
        }
    }
}

__global__ void __launch_bounds__(THREADS, 1) mlp_kernel(
    const float* __restrict__ x,
    const float* __restrict__ W0, const float* __restrict__ b0,
    const float* __restrict__ W2, const float* __restrict__ b2,
    const float* __restrict__ W3, const float* __restrict__ b3,
    float* __restrict__ out)
{
    extern __shared__ float smem[];
    float* s_act = smem;              // [128 k][128 node]   64 KB
    float* s_w   = smem + 128 * 128;  // [128 k][128 col]    64 KB

    const int tid = threadIdx.x;
    const int tx = tid & 15, ty = tid >> 4;
    const int j0 = tx * 8;            // output-column base
    const int n0 = ty * 8;            // node base (within block tile)
    const int nbase = blockIdx.x * TM;

    ull acc[4][8];                    // [node pair][col], lanes = 2 nodes
    #pragma unroll
    for (int p = 0; p < 4; ++p)
        #pragma unroll
        for (int j = 0; j < 8; ++j) acc[p][j] = 0ULL;

    // ---- Layer 1: K = 256 in two chunks (x cols, then edge_sum cols) ----
    #pragma unroll
    for (int c = 0; c < 2; ++c) {
        __syncthreads();
        load_act_t(s_act, c == 0 ? x : g_edge_sum, nbase, tid);
        load_w(s_w, W0 + (size_t)c * 128 * 128, tid);
        __syncthreads();
        gemm128(s_act, s_w, acc, n0, j0);
    }

    // epilogue 1: bias + ELU, store h1 transposed back into s_act
    {
        float bj[8];
        #pragma unroll
        for (int j = 0; j < 8; ++j) bj[j] = b0[j0 + j];
        __syncthreads();   // everyone done reading s_act / s_w of layer 1
        #pragma unroll
        for (int p = 0; p < 4; ++p)
            #pragma unroll
            for (int j = 0; j < 8; ++j) {
                float lo, hi; UNPK2(lo, hi, acc[p][j]);
                lo = elu1(lo + bj[j]);  hi = elu1(hi + bj[j]);
                *reinterpret_cast<float2*>(&s_act[(j0 + j) * TM + n0 + 2 * p]) =
                    make_float2(lo, hi);
                acc[p][j] = 0ULL;
            }
        load_w(s_w, W2, tid);
        __syncthreads();
    }

    // ---- Layer 2 ----
    gemm128(s_act, s_w, acc, n0, j0);
    {
        float bj[8];
        #pragma unroll
        for (int j = 0; j < 8; ++j) bj[j] = b2[j0 + j];
        __syncthreads();
        #pragma unroll
        for (int p = 0; p < 4; ++p)
            #pragma unroll
            for (int j = 0; j < 8; ++j) {
                float lo, hi; UNPK2(lo, hi, acc[p][j]);
                lo = elu1(lo + bj[j]);  hi = elu1(hi + bj[j]);
                *reinterpret_cast<float2*>(&s_act[(j0 + j) * TM + n0 + 2 * p]) =
                    make_float2(lo, hi);
                acc[p][j] = 0ULL;
            }
        load_w(s_w, W3, tid);
        __syncthreads();
    }

    // ---- Layer 3 (no activation) ----
    gemm128(s_act, s_w, acc, n0, j0);
    __syncthreads();   // done reading s_w -> reuse it as node-major out tile
    {
        float bj[8];
        #pragma unroll
        for (int j = 0; j < 8; ++j) bj[j] = b3[j0 + j];
        #pragma unroll
        for (int p = 0; p < 4; ++p)
            #pragma unroll
            for (int j = 0; j < 8; ++j) {
                float lo, hi; UNPK2(lo, hi, acc[p][j]);
                s_w[(n0 + 2 * p + 0) * C + j0 + j] = lo + bj[j];
                s_w[(n0 + 2 * p + 1) * C + j0 + j] = hi + bj[j];
            }
    }
    __syncthreads();

    // coalesced float4 write-out, tail-guarded
    #pragma unroll
    for (int i = tid; i < (TM * C) / 4; i += THREADS) {
        const int r = i >> 5;          // local node row
        const int node = nbase + r;
        if (node < N_NODES)
            reinterpret_cast<float4*>(out + (size_t)node * C)[i & 31] =
                reinterpret_cast<float4*>(s_w)[i];
    }
}

// ---------------------------------------------------------------------------
// Host launcher: dummy -> zero -> scatter -> fused MLP (one capture stream).
// ---------------------------------------------------------------------------
extern "C" void kernel_launch(void* const* d_in, const int* in_sizes, int n_in,
                              void* d_out, int out_size)
{
    const float* x  = (const float*)d_in[0];
    const int*   ei = (const int*)d_in[1];     // int32 edge_index, row 0 first
    const float* ea = (const float*)d_in[2];
    const float* W0 = (const float*)d_in[3];
    const float* b0 = (const float*)d_in[4];
    const float* W2 = (const float*)d_in[5];
    const float* b2 = (const float*)d_in[6];
    const float* W3 = (const float*)d_in[7];
    const float* b3 = (const float*)d_in[8];
    float* out = (float*)d_out;

    cudaFuncSetAttribute(mlp_kernel, cudaFuncAttributeMaxDynamicSharedMemorySize,
                         128 * 1024);

    dummy_kernel<<<1, 1>>>();   // keeps ncu's profiled slot on mlp_kernel
    zero_kernel<<<(N_NODES * C / 4 + 255) / 256, 256>>>();
    scatter_kernel<<<N_EDGES / 8, THREADS>>>(ea, ei);
    mlp_kernel<<<(N_NODES + TM - 1) / TM, THREADS, 128 * 1024>>>(
        x, W0, b0, W2, b2, W3, b3, out);
}

// round 17
// speedup vs baseline: 1.0296x; 1.0296x over previous
#include <cuda_runtime.h>
#include <cuda_bf16.h>

typedef unsigned long long ull;

#define N_NODES 50000
#define N_EDGES 800000
#define C 128            // channels (x dim, hidden, out)
#define TM  128          // nodes per block in MLP
#define THREADS 256

// 25.6 MB scratch for the per-node edge sums (cudaMalloc is forbidden).
__device__ float g_edge_sum[(size_t)N_NODES * C];

// ---------------------------------------------------------------------------
// Kernel 0: no-op. Keeps ncu's fixed profiled-launch slot on mlp_kernel.
// ---------------------------------------------------------------------------
__global__ void dummy_kernel() {}

// ---------------------------------------------------------------------------
// Kernel 1: zero the scatter target.
// ---------------------------------------------------------------------------
__global__ void zero_kernel() {
    int i = blockIdx.x * blockDim.x + threadIdx.x;   // float4 index
    if (i < (N_NODES * C) / 4)
        reinterpret_cast<float4*>(g_edge_sum)[i] = make_float4(0.f, 0.f, 0.f, 0.f);
}

// ---------------------------------------------------------------------------
// Kernel 2: scatter-add edge_attr rows into g_edge_sum[edge_index[0,e]].
// edge_index is INT32 (JAX x64 disabled -> int64 request yields int32).
// One warp per edge; each lane handles one float4 (512B/edge, coalesced read).
// ---------------------------------------------------------------------------
__global__ void __launch_bounds__(THREADS) scatter_kernel(
    const float* __restrict__ edge_attr,
    const int* __restrict__ edge_index)   // int32! row 0 = first N_EDGES entries
{
    const int e    = blockIdx.x * 8 + (threadIdx.x >> 5);
    const int lane = threadIdx.x & 31;
    const int n = edge_index[e];
    if ((unsigned)n >= (unsigned)N_NODES) return;   // defensive: never IMA
    const float4 v = reinterpret_cast<const float4*>(edge_attr)[(size_t)e * 32 + lane];
    float* dst = &g_edge_sum[(size_t)n * C + lane * 4];
    asm volatile("red.global.add.v4.f32 [%0], {%1, %2, %3, %4};"
                 :: "l"(dst), "f"(v.x), "f"(v.y), "f"(v.z), "f"(v.w)
                 : "memory");
}

// ---------------------------------------------------------------------------
// Kernel 3: fused 3-layer MLP with ELU, fp32 via packed fma.rn.f32x2.
// R16 + w-tile XOR swizzle: 16B unit u of each 512B row stored at
// u ^ ((u>>3)&1), turning the 4-way bank conflict of the stride-32B w-reads
// into the optimal 2-way (2 wavefronts per LDS.128 instead of 4).
// ---------------------------------------------------------------------------
__device__ __forceinline__ float elu1(float v) {
    return v > 0.f ? v : expm1f(v);
}

#define DUP2(d, s)  asm("mov.b64 %0, {%1, %1};" : "=l"(d) : "f"(s))
#define FMA2(acc, a, b) \
    asm("fma.rn.f32x2 %0, %1, %2, %0;" : "+l"(acc) : "l"(a), "l"(b))
#define UNPK2(lo, hi, s) \
    asm("mov.b64 {%0, %1}, %2;" : "=f"(lo), "=f"(hi) : "l"(s))

// Stage a [128 k][128 node] k-major activation tile from a row-major source.
__device__ __forceinline__ void load_act_t(float* s_act, const float* __restrict__ src,
                                           int nbase, int tid) {
    const int nl = tid & 127;
    int node = nbase + nl;
    if (node > N_NODES - 1) node = N_NODES - 1;   // clamp tail (stores guarded later)
    const float* row = src + (size_t)node * C;
    #pragma unroll
    for (int k0 = (tid >> 7) * 4; k0 < 128; k0 += 8) {
        const float4 v = *reinterpret_cast<const float4*>(row + k0);
        s_act[(k0 + 0) * TM + nl] = v.x;
        s_act[(k0 + 1) * TM + nl] = v.y;
        s_act[(k0 + 2) * TM + nl] = v.z;
        s_act[(k0 + 3) * TM + nl] = v.w;
    }
}

// Coalesced copy of a [128][128] fp32 weight tile into smem, XOR-swizzled:
// 16B unit u (0..31) of each row lands at u ^ ((u>>3)&1).
__device__ __forceinline__ void load_w(float* s_w, const float* __restrict__ W, int tid) {
    #pragma unroll
    for (int i = tid; i < (128 * 128) / 4; i += THREADS) {
        const int row = i >> 5;
        const int u   = i & 31;
        const int us  = u ^ ((u >> 3) & 1);
        reinterpret_cast<float4*>(s_w)[row * 32 + us] =
            reinterpret_cast<const float4*>(W)[i];
    }
}

// 8x8 register-tile GEMM over K=128; swizzled w reads, vector LDS a reads,
// one-k-ahead register prefetch.
__device__ __forceinline__ void gemm128(const float* s_act, const float* s_w,
                                        ull acc[4][8], int n0, int j0) {
    const int tx = j0 >> 3;
    const int s  = (tx >> 2) & 1;                 // swizzle bit for this thread
    const float* ar  = s_act + n0;                // + k*TM per step
    const float* wr0 = s_w + ((tx * 2 + 0) ^ s) * 4;   // + k*C per step
    const float* wr1 = s_w + ((tx * 2 + 1) ^ s) * 4;
    ulonglong2 A01 = *reinterpret_cast<const ulonglong2*>(ar);
    ulonglong2 A23 = *reinterpret_cast<const ulonglong2*>(ar + 4);
    float4     W0  = *reinterpret_cast<const float4*>(wr0);
    float4     W1  = *reinterpret_cast<const float4*>(wr1);
    #pragma unroll 8
    for (int k = 0; k < 128; ++k) {
        const ulonglong2 a01 = A01, a23 = A23;
        const float4     w0  = W0,  w1  = W1;
        if (k + 1 < 128) {          // prefetch next k before this k's math
            const float* arn = ar + (k + 1) * TM;
            A01 = *reinterpret_cast<const ulonglong2*>(arn);
            A23 = *reinterpret_cast<const ulonglong2*>(arn + 4);
            W0  = *reinterpret_cast<const float4*>(wr0 + (k + 1) * C);
            W1  = *reinterpret_cast<const float4*>(wr1 + (k + 1) * C);
        }
        ull wd[8];
        DUP2(wd[0], w0.x); DUP2(wd[1], w0.y); DUP2(wd[2], w0.z); DUP2(wd[3], w0.w);
        DUP2(wd[4], w1.x); DUP2(wd[5], w1.y); DUP2(wd[6], w1.z); DUP2(wd[7], w1.w);
        #pragma unroll
        for (int j = 0; j < 8; ++j) {
            FMA2(acc[0][j], a01.x, wd[j]);
            FMA2(acc[1][j], a01.y, wd[j]);
            FMA2(acc[2][j], a23.x, wd[j]);
            FMA2(acc[3][j], a23.y, wd[j]);
        }
    }
}

__global__ void __launch_bounds__(THREADS, 1) mlp_kernel(
    const float* __restrict__ x,
    const float* __restrict__ W0, const float* __restrict__ b0,
    const float* __restrict__ W2, const float* __restrict__ b2,
    const float* __restrict__ W3, const float* __restrict__ b3,
    float* __restrict__ out)
{
    extern __shared__ float smem[];
    float* s_act = smem;              // [128 k][128 node]   64 KB
    float* s_w   = smem + 128 * 128;  // [128 k][128 col]    64 KB (swizzled)

    const int tid = threadIdx.x;
    const int tx = tid & 15, ty = tid >> 4;
    const int j0 = tx * 8;            // output-column base
    const int n0 = ty * 8;            // node base (within block tile)
    const int nbase = blockIdx.x * TM;

    ull acc[4][8];                    // [node pair][col], lanes = 2 nodes
    #pragma unroll
    for (int p = 0; p < 4; ++p)
        #pragma unroll
        for (int j = 0; j < 8; ++j) acc[p][j] = 0ULL;

    // ---- Layer 1: K = 256 in two chunks (x cols, then edge_sum cols) ----
    #pragma unroll
    for (int c = 0; c < 2; ++c) {
        __syncthreads();
        load_act_t(s_act, c == 0 ? x : g_edge_sum, nbase, tid);
        load_w(s_w, W0 + (size_t)c * 128 * 128, tid);
        __syncthreads();
        gemm128(s_act, s_w, acc, n0, j0);
    }

    // epilogue 1: bias + ELU, store h1 transposed back into s_act
    {
        float bj[8];
        #pragma unroll
        for (int j = 0; j < 8; ++j) bj[j] = b0[j0 + j];
        __syncthreads();   // everyone done reading s_act / s_w of layer 1
        #pragma unroll
        for (int p = 0; p < 4; ++p)
            #pragma unroll
            for (int j = 0; j < 8; ++j) {
                float lo, hi; UNPK2(lo, hi, acc[p][j]);
                lo = elu1(lo + bj[j]);  hi = elu1(hi + bj[j]);
                *reinterpret_cast<float2*>(&s_act[(j0 + j) * TM + n0 + 2 * p]) =
                    make_float2(lo, hi);
                acc[p][j] = 0ULL;
            }
        load_w(s_w, W2, tid);
        __syncthreads();
    }

    // ---- Layer 2 ----
    gemm128(s_act, s_w, acc, n0, j0);
    {
        float bj[8];
        #pragma unroll
        for (int j = 0; j < 8; ++j) bj[j] = b2[j0 + j];
        __syncthreads();
        #pragma unroll
        for (int p = 0; p < 4; ++p)
            #pragma unroll
            for (int j = 0; j < 8; ++j) {
                float lo, hi; UNPK2(lo, hi, acc[p][j]);
                lo = elu1(lo + bj[j]);  hi = elu1(hi + bj[j]);
                *reinterpret_cast<float2*>(&s_act[(j0 + j) * TM + n0 + 2 * p]) =
                    make_float2(lo, hi);
                acc[p][j] = 0ULL;
            }
        load_w(s_w, W3, tid);
        __syncthreads();
    }

    // ---- Layer 3 (no activation) ----
    gemm128(s_act, s_w, acc, n0, j0);
    __syncthreads();   // done reading s_w -> reuse it as node-major out tile
    {
        float bj[8];
        #pragma unroll
        for (int j = 0; j < 8; ++j) bj[j] = b3[j0 + j];
        #pragma unroll
        for (int p = 0; p < 4; ++p)
            #pragma unroll
            for (int j = 0; j < 8; ++j) {
                float lo, hi; UNPK2(lo, hi, acc[p][j]);
                s_w[(n0 + 2 * p + 0) * C + j0 + j] = lo + bj[j];
                s_w[(n0 + 2 * p + 1) * C + j0 + j] = hi + bj[j];
            }
    }
    __syncthreads();

    // coalesced float4 write-out, tail-guarded
    #pragma unroll
    for (int i = tid; i < (TM * C) / 4; i += THREADS) {
        const int r = i >> 5;          // local node row
        const int node = nbase + r;
        if (node < N_NODES)
            reinterpret_cast<float4*>(out + (size_t)node * C)[i & 31] =
                reinterpret_cast<float4*>(s_w)[i];
    }
}

// ---------------------------------------------------------------------------
// Host launcher: dummy -> zero -> scatter -> fused MLP (one capture stream).
// ---------------------------------------------------------------------------
extern "C" void kernel_launch(void* const* d_in, const int* in_sizes, int n_in,
                              void* d_out, int out_size)
{
    const float* x  = (const float*)d_in[0];
    const int*   ei = (const int*)d_in[1];     // int32 edge_index, row 0 first
    const float* ea = (const float*)d_in[2];
    const float* W0 = (const float*)d_in[3];
    const float* b0 = (const float*)d_in[4];
    const float* W2 = (const float*)d_in[5];
    const float* b2 = (const float*)d_in[6];
    const float* W3 = (const float*)d_in[7];
    const float* b3 = (const float*)d_in[8];
    float* out = (float*)d_out;

    cudaFuncSetAttribute(mlp_kernel, cudaFuncAttributeMaxDynamicSharedMemorySize,
                         128 * 1024);

    dummy_kernel<<<1, 1>>>();   // keeps ncu's profiled slot on mlp_kernel
    zero_kernel<<<(N_NODES * C / 4 + 255) / 256, 256>>>();
    scatter_kernel<<<N_EDGES / 8, THREADS>>>(ea, ei);
    mlp_kernel<<<(N_NODES + TM - 1) / TM, THREADS, 128 * 1024>>>(
        x, W0, b0, W2, b2, W3, b3, out);
}